// round 4
// baseline (speedup 1.0000x reference)
#include <cuda_runtime.h>
#include <cstdint>

// ============================================================================
// out[M,N] = ((x - X_ZP)*Xs) @ ((y - Y_ZP)*Ys),  M=N=K=4096
//   x int32 in [-128,127] -> s8 ;  y int32 in [0,255] -> u8
// out = S * ( x@y  - Y_ZP*rowsum(x)[m] - X_ZP*colsum(y)[n] + X_ZP*Y_ZP*K )
//   S = 0.03*0.025 = 7.5e-4 ; X_ZP=-66, Y_ZP=160
//   => out_int = dot - 160*Sx[m] + 66*Sy[n] - 43253760   (exact in int32)
// GEMM: mma.sync.aligned.m16n8k32.row.col.s32.s8.u8.s32 (base sm_103 target;
// tcgen05 is rejected by this harness's ptxas target).
// A/B pre-packed in register-fragment order => linear cp.async, LDS.128 frags.
// ============================================================================

#define MDIM 4096
#define NDIM 4096
#define KDIM 4096

#define BM 128
#define BN 256
#define BK 64
#define STAGES 4
#define KITERS (KDIM / BK)          // 64
#define THREADS 256

#define A_STAGE_BYTES (BM * BK)     // 8192
#define B_STAGE_BYTES (BN * BK)     // 16384
#define STAGE_BYTES   (A_STAGE_BYTES + B_STAGE_BYTES)   // 24576
#define SMEM_TOTAL    (STAGES * STAGE_BYTES)            // 98304

#define KBLOCKS (KDIM / BK)         // 64
#define A_BLOCK_BYTES 8192          // per (mb,kb): 8 mtiles * 2 ktiles * 512
#define B_BLOCK_BYTES 16384         // per (nb,kb): 32 ntiles * 2 ktiles * 256

#define OUT_SCALE 0.00075f
#define CONST_TERM 43253760         // 66*160*4096

// ---------------------------------------------------------------------------
// Scratch (__device__ globals -- allocation free)
// ---------------------------------------------------------------------------
__device__ uint8_t g_A[(size_t)MDIM * KDIM];   // s8 bits, fragment-packed
__device__ uint8_t g_B[(size_t)NDIM * KDIM];   // u8, fragment-packed
__device__ int     g_Sx[MDIM];
__device__ int     g_Sy[NDIM];

// ---------------------------------------------------------------------------
// PTX helpers
// ---------------------------------------------------------------------------
__device__ __forceinline__ uint32_t smem_to_u32(const void* p) {
    uint32_t a;
    asm("{ .reg .u64 t; cvta.to.shared.u64 t, %1; cvt.u32.u64 %0, t; }"
        : "=r"(a) : "l"(p));
    return a;
}

#define CP_ASYNC16(dst, src) \
    asm volatile("cp.async.cg.shared.global [%0], [%1], 16;" :: "r"(dst), "l"(src))
#define CP_COMMIT() asm volatile("cp.async.commit_group;" ::: "memory")
#define CP_WAIT(n)  asm volatile("cp.async.wait_group %0;" :: "n"(n) : "memory")

__device__ __forceinline__ void imma16832(int* d, const uint32_t* a, const uint32_t* b) {
    asm volatile(
        "mma.sync.aligned.m16n8k32.row.col.s32.s8.u8.s32 "
        "{%0,%1,%2,%3}, {%4,%5,%6,%7}, {%8,%9}, {%0,%1,%2,%3};"
        : "+r"(d[0]), "+r"(d[1]), "+r"(d[2]), "+r"(d[3])
        : "r"(a[0]), "r"(a[1]), "r"(a[2]), "r"(a[3]), "r"(b[0]), "r"(b[1]));
}

// ---------------------------------------------------------------------------
// Kernel: pack x -> s8 fragment layout, compute row sums Sx
//   grid = M/16 blocks, 256 threads. Thread t: row r = t>>4, kt = t&15.
// Fragment addressing (A, m16k32 tile = 512B):
//   lane = (row&7)*4 + ((k&15)>>2), reg = (row>>3) | (((k>>4)&1)<<1), byte=k&3
//   addr = (mb*KBLOCKS + kb)*8192 + ((mtile*2 + ktile)<<9) + lane*16 + reg*4
// ---------------------------------------------------------------------------
__global__ void convert_x_kernel(const int* __restrict__ x) {
    int band = blockIdx.x;            // m/16
    int m0 = band * 16;
    int t = threadIdx.x;
    int r = t >> 4;                   // 0..15
    int kt = t & 15;
    int mb = band >> 3;
    int mtile = band & 7;
    const int4* __restrict__ row = (const int4*)(x + (size_t)(m0 + r) * KDIM);
    uint32_t mbase = (uint32_t)(mb * KBLOCKS) * A_BLOCK_BYTES;
    uint32_t lane_hi = (uint32_t)((r & 7) << 2);
    uint32_t reg_lo = (uint32_t)(r >> 3);
    int sum = 0;
    #pragma unroll 4
    for (int j = 0; j < 64; j++) {
        int w = kt + j * 16;          // int4 index; k = w*4
        int4 v = row[w];
        sum += v.x + v.y + v.z + v.w;
        int k = w * 4;
        uint32_t kb = (uint32_t)(k >> 6);
        uint32_t ktile = (uint32_t)((k >> 5) & 1);
        uint32_t ln = lane_hi | (uint32_t)((k & 15) >> 2);
        uint32_t rg = reg_lo | (uint32_t)(((k >> 4) & 1) << 1);
        char4 c;
        c.x = (char)v.x; c.y = (char)v.y; c.z = (char)v.z; c.w = (char)v.w;
        uint32_t addr = mbase + kb * A_BLOCK_BYTES
                      + (((uint32_t)mtile * 2 + ktile) << 9) + ln * 16 + rg * 4;
        *reinterpret_cast<char4*>(g_A + addr) = c;
    }
    // reduce over the 16 kt-lanes of this row
    #pragma unroll
    for (int off = 8; off; off >>= 1)
        sum += __shfl_down_sync(0xFFFFFFFFu, sum, off, 16);
    if (kt == 0) g_Sx[m0 + r] = sum;
}

// ---------------------------------------------------------------------------
// Kernel: transpose+pack y -> u8 fragment layout
//   grid = (N/64, K/32), 256 threads; tile 32k x 64n via smem.
// Fragment addressing (B, n8k32 tile = 256B):
//   lane = (n&7)*4 + ((k&15)>>2), reg = (k>>4)&1, byte=k&3
//   addr = (nb*KBLOCKS + kb)*16384 + (ntile*2 + ktile)*256 + lane*8 + reg*4
// ---------------------------------------------------------------------------
__global__ void convert_y_kernel(const int* __restrict__ y) {
    __shared__ int s[32][65];
    int n0 = blockIdx.x * 64;
    int k0 = blockIdx.y * 32;
    int t = threadIdx.x;
    #pragma unroll
    for (int i = 0; i < 8; i++) {
        int idx = t + i * 256;
        int kk = idx >> 6, nn = idx & 63;
        s[kk][nn] = y[(size_t)(k0 + kk) * NDIM + (n0 + nn)];
    }
    __syncthreads();
    #pragma unroll
    for (int i = 0; i < 2; i++) {
        int w = t + i * 256;          // 0..511
        int n = w >> 3;               // 0..63 (local)
        int kg = w & 7;               // k-quad: k = kg*4 (local)
        int ng = n0 + n;
        int kgl = k0 + kg * 4;
        uchar4 c;
        c.x = (unsigned char)s[kg * 4 + 0][n];
        c.y = (unsigned char)s[kg * 4 + 1][n];
        c.z = (unsigned char)s[kg * 4 + 2][n];
        c.w = (unsigned char)s[kg * 4 + 3][n];
        uint32_t nb = (uint32_t)(ng >> 8);
        uint32_t ntile = (uint32_t)((ng >> 3) & 31);
        uint32_t kb = (uint32_t)(kgl >> 6);
        uint32_t ktile = (uint32_t)((kgl >> 5) & 1);
        uint32_t ln = (uint32_t)(((ng & 7) << 2) | ((kgl & 15) >> 2));
        uint32_t rg = (uint32_t)((kgl >> 4) & 1);
        uint32_t addr = (nb * KBLOCKS + kb) * B_BLOCK_BYTES
                      + (ntile * 2 + ktile) * 256 + ln * 8 + rg * 4;
        *reinterpret_cast<uchar4*>(g_B + addr) = c;
    }
}

// ---------------------------------------------------------------------------
// Column sums of y: Sy[n] = sum_k y[k][n].  Needs g_Sy pre-zeroed.
// ---------------------------------------------------------------------------
__global__ void zero_sy_kernel() {
    g_Sy[blockIdx.x * 256 + threadIdx.x] = 0;
}

__global__ void sy_kernel(const int* __restrict__ y) {
    int n = blockIdx.x * 256 + threadIdx.x;
    int k0 = blockIdx.y * 128;
    const int* p = y + (size_t)k0 * NDIM + n;
    int s = 0;
    #pragma unroll 8
    for (int k = 0; k < 128; k++) s += p[(size_t)k * NDIM];
    atomicAdd(&g_Sy[n], s);
}

// ---------------------------------------------------------------------------
// GEMM: 128x256x4096, s8 x u8 -> s32 via mma.sync m16n8k32
// 256 threads = 8 warps (2 m x 4 n), warp tile 64x64.
// ---------------------------------------------------------------------------
__device__ __forceinline__ void load_stage(uint32_t sbase, const uint8_t* Ag,
                                           const uint8_t* Bg, int t) {
    #pragma unroll
    for (int i = 0; i < 2; i++) {
        int c = t + i * THREADS;
        CP_ASYNC16(sbase + c * 16, Ag + c * 16);
    }
    #pragma unroll
    for (int i = 0; i < 4; i++) {
        int c = t + i * THREADS;
        CP_ASYNC16(sbase + A_STAGE_BYTES + c * 16, Bg + c * 16);
    }
}

__global__ void __launch_bounds__(THREADS, 1)
gemm_kernel(float* __restrict__ out) {
    extern __shared__ uint8_t smem[];
    uint32_t sm0 = smem_to_u32(smem);
    int t = threadIdx.x;
    int wid = t >> 5;
    int lane = t & 31;
    int wm = wid & 1;                 // 2 warps along M
    int wn = wid >> 1;                // 4 warps along N

    int mb = blockIdx.y;              // M block (BM=128)
    int nb = blockIdx.x;              // N block (BN=256)
    const uint8_t* Ag = g_A + (size_t)(mb * KBLOCKS) * A_BLOCK_BYTES;
    const uint8_t* Bg = g_B + (size_t)(nb * KBLOCKS) * B_BLOCK_BYTES;

    int acc[4][8][4];
    #pragma unroll
    for (int i = 0; i < 4; i++)
        #pragma unroll
        for (int j = 0; j < 8; j++)
            #pragma unroll
            for (int c = 0; c < 4; c++) acc[i][j][c] = 0;

    // prologue: fill STAGES-1 stages
    #pragma unroll
    for (int s = 0; s < STAGES - 1; s++) {
        load_stage(sm0 + s * STAGE_BYTES, Ag + s * A_BLOCK_BYTES,
                   Bg + s * B_BLOCK_BYTES, t);
        CP_COMMIT();
    }

    for (int i = 0; i < KITERS; i++) {
        CP_WAIT(STAGES - 2);
        __syncthreads();

        int s = i & (STAGES - 1);
        uint32_t sA = sm0 + s * STAGE_BYTES;
        uint32_t sB = sA + A_STAGE_BYTES;

        #pragma unroll
        for (int kt = 0; kt < 2; kt++) {
            uint32_t a[4][4], b[8][2];
            #pragma unroll
            for (int mi = 0; mi < 4; mi++) {
                uint32_t off = sA + (((uint32_t)(wm * 4 + mi) * 2 + kt) << 9)
                             + (uint32_t)lane * 16;
                uint4 v;
                asm volatile("ld.shared.v4.b32 {%0,%1,%2,%3}, [%4];"
                             : "=r"(v.x), "=r"(v.y), "=r"(v.z), "=r"(v.w) : "r"(off));
                a[mi][0] = v.x; a[mi][1] = v.y; a[mi][2] = v.z; a[mi][3] = v.w;
            }
            #pragma unroll
            for (int nj = 0; nj < 8; nj++) {
                uint32_t off = sB + (((uint32_t)(wn * 8 + nj) * 2 + kt) << 8)
                             + (uint32_t)lane * 8;
                uint2 v;
                asm volatile("ld.shared.v2.b32 {%0,%1}, [%2];"
                             : "=r"(v.x), "=r"(v.y) : "r"(off));
                b[nj][0] = v.x; b[nj][1] = v.y;
            }
            #pragma unroll
            for (int mi = 0; mi < 4; mi++)
                #pragma unroll
                for (int nj = 0; nj < 8; nj++)
                    imma16832(acc[mi][nj], a[mi], b[nj]);
        }

        int j = i + STAGES - 1;
        if (j < KITERS) {
            int sj = j & (STAGES - 1);
            load_stage(sm0 + sj * STAGE_BYTES, Ag + j * A_BLOCK_BYTES,
                       Bg + (size_t)j * B_BLOCK_BYTES, t);
        }
        CP_COMMIT();
    }

    // ---------------- epilogue: zero-point corrections + scale -------------
    int g = lane >> 2;                // 0..7 (row in tile)
    int tg = lane & 3;                // col pair selector
    int mBase = mb * BM + wm * 64;
    int nBase = nb * BN + wn * 64;

    int rowc[8];
    #pragma unroll
    for (int mi = 0; mi < 4; mi++)
        #pragma unroll
        for (int h = 0; h < 2; h++)
            rowc[mi * 2 + h] = -160 * g_Sx[mBase + mi * 16 + h * 8 + g] - CONST_TERM;

    int colc[16];
    #pragma unroll
    for (int nj = 0; nj < 8; nj++)
        #pragma unroll
        for (int c = 0; c < 2; c++)
            colc[nj * 2 + c] = 66 * g_Sy[nBase + nj * 8 + tg * 2 + c];

    #pragma unroll
    for (int mi = 0; mi < 4; mi++) {
        #pragma unroll
        for (int h = 0; h < 2; h++) {
            int m = mBase + mi * 16 + h * 8 + g;
            float* orow = out + (size_t)m * NDIM;
            #pragma unroll
            for (int nj = 0; nj < 8; nj++) {
                int n = nBase + nj * 8 + tg * 2;
                float2 o;
                o.x = OUT_SCALE * (float)(acc[mi][nj][h * 2 + 0] + rowc[mi * 2 + h] + colc[nj * 2 + 0]);
                o.y = OUT_SCALE * (float)(acc[mi][nj][h * 2 + 1] + rowc[mi * 2 + h] + colc[nj * 2 + 1]);
                *reinterpret_cast<float2*>(orow + n) = o;
            }
        }
    }
}

// ---------------------------------------------------------------------------
// Launch
// ---------------------------------------------------------------------------
extern "C" void kernel_launch(void* const* d_in, const int* in_sizes, int n_in,
                              void* d_out, int out_size) {
    const int* x = (const int*)d_in[0];
    const int* y = (const int*)d_in[1];
    float* out = (float*)d_out;

    static int configured = 0;
    cudaFuncSetAttribute(gemm_kernel, cudaFuncAttributeMaxDynamicSharedMemorySize,
                         SMEM_TOTAL);
    (void)configured;

    zero_sy_kernel<<<NDIM / 256, 256>>>();
    convert_x_kernel<<<MDIM / 16, 256>>>(x);
    convert_y_kernel<<<dim3(NDIM / 64, KDIM / 32), 256>>>(y);
    sy_kernel<<<dim3(NDIM / 256, KDIM / 128), 256>>>(y);

    gemm_kernel<<<dim3(NDIM / BN, MDIM / BM), THREADS, SMEM_TOTAL>>>(out);
}

// round 5
// speedup vs baseline: 1.0147x; 1.0147x over previous
#include <cuda_runtime.h>
#include <cstdint>

// ============================================================================
// out[M,N] = ((x - X_ZP)*Xs) @ ((y - Y_ZP)*Ys),  M=N=K=4096
//   x int32 in [-128,127] -> s8 ;  y int32 in [0,255] -> u8
// out = S * ( x@y - 160*Sx[m] + 66*Sy[n] - 66*160*4096 ), S = 7.5e-4 (exact)
// GEMM: mma.sync.aligned.m16n8k32.row.col.s32.s8.u8.s32
// A/B pre-packed in register-fragment order => linear cp.async, LDS.128 frags.
// R4 changes: 512 threads / 16 warps (warp tile 64x32, acc=64 regs),
//             B packed with both k-halves per 16B lane chunk (v4 frag loads),
//             cp.async issued before compute, 3-launch sequence.
// ============================================================================

#define MDIM 4096
#define NDIM 4096
#define KDIM 4096

#define BM 128
#define BN 256
#define BK 64
#define STAGES 4
#define KITERS (KDIM / BK)          // 64
#define THREADS 512

#define A_STAGE_BYTES (BM * BK)     // 8192
#define B_STAGE_BYTES (BN * BK)     // 16384
#define STAGE_BYTES   (A_STAGE_BYTES + B_STAGE_BYTES)   // 24576
#define SMEM_TOTAL    (STAGES * STAGE_BYTES)            // 98304

#define KBLOCKS (KDIM / BK)         // 64
#define A_BLOCK_BYTES 8192          // per (mb,kb): 8 mtiles * 2 ktiles * 512
#define B_BLOCK_BYTES 16384         // per (nb,kb): 32 ntiles * 512

#define OUT_SCALE 0.00075f
#define CONST_TERM 43253760         // 66*160*4096

// ---------------------------------------------------------------------------
// Scratch (__device__ globals -- allocation free)
// ---------------------------------------------------------------------------
__device__ uint8_t g_A[(size_t)MDIM * KDIM];   // s8 bits, fragment-packed
__device__ uint8_t g_B[(size_t)NDIM * KDIM];   // u8, fragment-packed
__device__ int     g_Sx[MDIM];
__device__ int     g_Sy[NDIM];

// ---------------------------------------------------------------------------
// PTX helpers
// ---------------------------------------------------------------------------
__device__ __forceinline__ uint32_t smem_to_u32(const void* p) {
    uint32_t a;
    asm("{ .reg .u64 t; cvta.to.shared.u64 t, %1; cvt.u32.u64 %0, t; }"
        : "=r"(a) : "l"(p));
    return a;
}

#define CP_ASYNC16(dst, src) \
    asm volatile("cp.async.cg.shared.global [%0], [%1], 16;" :: "r"(dst), "l"(src))
#define CP_COMMIT() asm volatile("cp.async.commit_group;" ::: "memory")
#define CP_WAIT(n)  asm volatile("cp.async.wait_group %0;" :: "n"(n) : "memory")

__device__ __forceinline__ void imma16832(int* d, const uint32_t* a,
                                          uint32_t b0, uint32_t b1) {
    asm volatile(
        "mma.sync.aligned.m16n8k32.row.col.s32.s8.u8.s32 "
        "{%0,%1,%2,%3}, {%4,%5,%6,%7}, {%8,%9}, {%0,%1,%2,%3};"
        : "+r"(d[0]), "+r"(d[1]), "+r"(d[2]), "+r"(d[3])
        : "r"(a[0]), "r"(a[1]), "r"(a[2]), "r"(a[3]), "r"(b0), "r"(b1));
}

// ---------------------------------------------------------------------------
// Kernel 1: pack x -> s8 fragment layout, row sums Sx, and zero Sy.
//   grid = M/16 = 256 blocks, 256 threads. Thread t: row r = t>>4, kt = t&15.
// A fragment addressing (m16k32 tile = 512B):
//   lane = (row&7)*4 + ((k&15)>>2), reg = (row>>3) | (((k>>4)&1)<<1)
//   addr = (mb*KBLOCKS + kb)*8192 + ((mtile*2 + ktile)<<9) + lane*16 + reg*4
// ---------------------------------------------------------------------------
__global__ void convert_x_kernel(const int* __restrict__ x) {
    int band = blockIdx.x;            // m/16
    int m0 = band * 16;
    int t = threadIdx.x;
    if (band < 16) g_Sy[band * 256 + t] = 0;   // zero Sy (16*256 = 4096)
    int r = t >> 4;                   // 0..15
    int kt = t & 15;
    int mb = band >> 3;
    int mtile = band & 7;
    const int4* __restrict__ row = (const int4*)(x + (size_t)(m0 + r) * KDIM);
    uint32_t mbase = (uint32_t)(mb * KBLOCKS) * A_BLOCK_BYTES;
    uint32_t lane_hi = (uint32_t)((r & 7) << 2);
    uint32_t reg_lo = (uint32_t)(r >> 3);
    int sum = 0;
    #pragma unroll 4
    for (int j = 0; j < 64; j++) {
        int w = kt + j * 16;          // int4 index; k = w*4
        int4 v = row[w];
        sum += v.x + v.y + v.z + v.w;
        int k = w * 4;
        uint32_t kb = (uint32_t)(k >> 6);
        uint32_t ktile = (uint32_t)((k >> 5) & 1);
        uint32_t ln = lane_hi | (uint32_t)((k & 15) >> 2);
        uint32_t rg = reg_lo | (uint32_t)(((k >> 4) & 1) << 1);
        char4 c;
        c.x = (char)v.x; c.y = (char)v.y; c.z = (char)v.z; c.w = (char)v.w;
        uint32_t addr = mbase + kb * A_BLOCK_BYTES
                      + (((uint32_t)mtile * 2 + ktile) << 9) + ln * 16 + rg * 4;
        *reinterpret_cast<char4*>(g_A + addr) = c;
    }
    #pragma unroll
    for (int off = 8; off; off >>= 1)
        sum += __shfl_down_sync(0xFFFFFFFFu, sum, off, 16);
    if (kt == 0) g_Sx[m0 + r] = sum;
}

// ---------------------------------------------------------------------------
// Kernel 2: transpose+pack y -> u8 fragment layout + column sums Sy (atomic).
//   grid = (N/64, K/32), 256 threads; tile 32k x 64n via smem.
// B fragment addressing (n8 tile spanning BOTH k-halves = 512B):
//   lane = (n&7)*4 + ((k&15)>>2)
//   addr = (nb*KBLOCKS+kb)*16384 + ntile*512 + lane*16 + ktile*8 + reg*4
//   where ktile=(k>>5)&1, reg=(k>>4)&1  -> one LDS.128 per (ntile) covers
//   {kt0.r0, kt0.r1, kt1.r0, kt1.r1}.
// ---------------------------------------------------------------------------
__global__ void convert_y_kernel(const int* __restrict__ y) {
    __shared__ int s[32][65];
    int n0 = blockIdx.x * 64;
    int k0 = blockIdx.y * 32;
    int t = threadIdx.x;
    #pragma unroll
    for (int i = 0; i < 8; i++) {
        int idx = t + i * 256;
        int kk = idx >> 6, nn = idx & 63;
        s[kk][nn] = y[(size_t)(k0 + kk) * NDIM + (n0 + nn)];
    }
    __syncthreads();
    // pack
    #pragma unroll
    for (int i = 0; i < 2; i++) {
        int w = t + i * 256;          // 0..511
        int n = w >> 3;               // 0..63 (local)
        int kg = w & 7;               // k-quad: local k = kg*4
        int ng = n0 + n;
        int kgl = k0 + kg * 4;
        uchar4 c;
        c.x = (unsigned char)s[kg * 4 + 0][n];
        c.y = (unsigned char)s[kg * 4 + 1][n];
        c.z = (unsigned char)s[kg * 4 + 2][n];
        c.w = (unsigned char)s[kg * 4 + 3][n];
        uint32_t nb = (uint32_t)(ng >> 8);
        uint32_t ntile = (uint32_t)((ng >> 3) & 31);
        uint32_t kb = (uint32_t)(kgl >> 6);
        uint32_t ktile = (uint32_t)((kgl >> 5) & 1);
        uint32_t rg = (uint32_t)((kgl >> 4) & 1);
        uint32_t ln = (uint32_t)(((ng & 7) << 2) | ((kgl & 15) >> 2));
        uint32_t addr = (nb * KBLOCKS + kb) * B_BLOCK_BYTES
                      + ntile * 512 + ln * 16 + ktile * 8 + rg * 4;
        *reinterpret_cast<uchar4*>(g_B + addr) = c;
    }
    // column sums: thread t -> n = t>>2, k-range (t&3)*8..+8
    {
        int n = t >> 2;
        int ks = (t & 3) * 8;
        int sum = 0;
        #pragma unroll
        for (int k = 0; k < 8; k++) sum += s[ks + k][n];
        #pragma unroll
        for (int off = 2; off; off >>= 1)
            sum += __shfl_down_sync(0xFFFFFFFFu, sum, off, 4);
        if ((t & 3) == 0) atomicAdd(&g_Sy[n0 + n], sum);
    }
}

// ---------------------------------------------------------------------------
// GEMM: 128x256x4096 per CTA, 512 threads = 16 warps (2m x 8n), warp 64x32.
// ---------------------------------------------------------------------------
__device__ __forceinline__ void load_stage(uint32_t sbase, const uint8_t* Ag,
                                           const uint8_t* Bg, int t) {
    // A: 8192B = 512 x 16B, one per thread
    CP_ASYNC16(sbase + t * 16, Ag + t * 16);
    // B: 16384B = 1024 x 16B, two per thread
    #pragma unroll
    for (int i = 0; i < 2; i++) {
        int c = t + i * THREADS;
        CP_ASYNC16(sbase + A_STAGE_BYTES + c * 16, Bg + c * 16);
    }
}

__global__ void __launch_bounds__(THREADS, 1)
gemm_kernel(float* __restrict__ out) {
    extern __shared__ uint8_t smem[];
    uint32_t sm0 = smem_to_u32(smem);
    int t = threadIdx.x;
    int wid = t >> 5;
    int lane = t & 31;
    int wm = wid & 1;                 // 2 warps along M (64 rows each)
    int wn = wid >> 1;                // 8 warps along N (32 cols each)

    int mb = blockIdx.y;
    int nb = blockIdx.x;
    const uint8_t* Ag = g_A + (size_t)(mb * KBLOCKS) * A_BLOCK_BYTES;
    const uint8_t* Bg = g_B + (size_t)(nb * KBLOCKS) * B_BLOCK_BYTES;

    int acc[4][4][4];
    #pragma unroll
    for (int i = 0; i < 4; i++)
        #pragma unroll
        for (int j = 0; j < 4; j++)
            #pragma unroll
            for (int c = 0; c < 4; c++) acc[i][j][c] = 0;

    #pragma unroll
    for (int s = 0; s < STAGES - 1; s++) {
        load_stage(sm0 + s * STAGE_BYTES, Ag + s * A_BLOCK_BYTES,
                   Bg + (size_t)s * B_BLOCK_BYTES, t);
        CP_COMMIT();
    }

    for (int i = 0; i < KITERS; i++) {
        CP_WAIT(STAGES - 2);
        __syncthreads();

        int s = i & (STAGES - 1);
        uint32_t sA = sm0 + s * STAGE_BYTES;
        uint32_t sB = sA + A_STAGE_BYTES;

        // issue next-stage loads FIRST so they overlap the compute below
        int j = i + STAGES - 1;
        if (j < KITERS) {
            int sj = j & (STAGES - 1);
            load_stage(sm0 + sj * STAGE_BYTES, Ag + j * A_BLOCK_BYTES,
                       Bg + (size_t)j * B_BLOCK_BYTES, t);
        }
        CP_COMMIT();

        // B fragments: one v4 per ntile covers both k-halves
        uint32_t b[4][4];
        #pragma unroll
        for (int nj = 0; nj < 4; nj++) {
            uint32_t off = sB + (uint32_t)(wn * 4 + nj) * 512 + (uint32_t)lane * 16;
            asm volatile("ld.shared.v4.b32 {%0,%1,%2,%3}, [%4];"
                         : "=r"(b[nj][0]), "=r"(b[nj][1]), "=r"(b[nj][2]), "=r"(b[nj][3])
                         : "r"(off));
        }
        #pragma unroll
        for (int kt = 0; kt < 2; kt++) {
            uint32_t a[4][4];
            #pragma unroll
            for (int mi = 0; mi < 4; mi++) {
                uint32_t off = sA + (((uint32_t)(wm * 4 + mi) * 2 + kt) << 9)
                             + (uint32_t)lane * 16;
                asm volatile("ld.shared.v4.b32 {%0,%1,%2,%3}, [%4];"
                             : "=r"(a[mi][0]), "=r"(a[mi][1]), "=r"(a[mi][2]), "=r"(a[mi][3])
                             : "r"(off));
            }
            #pragma unroll
            for (int mi = 0; mi < 4; mi++)
                #pragma unroll
                for (int nj = 0; nj < 4; nj++)
                    imma16832(acc[mi][nj], a[mi], b[nj][kt * 2], b[nj][kt * 2 + 1]);
        }
    }

    // ---------------- epilogue: zero-point corrections + scale -------------
    int g = lane >> 2;                // 0..7 (row in 8-row group)
    int tg = lane & 3;                // col pair selector
    int mBase = mb * BM + wm * 64;
    int nBase = nb * BN + wn * 32;

    int rowc[8];
    #pragma unroll
    for (int mi = 0; mi < 4; mi++)
        #pragma unroll
        for (int h = 0; h < 2; h++)
            rowc[mi * 2 + h] = -160 * g_Sx[mBase + mi * 16 + h * 8 + g] - CONST_TERM;

    int colc[8];
    #pragma unroll
    for (int nj = 0; nj < 4; nj++)
        #pragma unroll
        for (int c = 0; c < 2; c++)
            colc[nj * 2 + c] = 66 * g_Sy[nBase + nj * 8 + tg * 2 + c];

    #pragma unroll
    for (int mi = 0; mi < 4; mi++) {
        #pragma unroll
        for (int h = 0; h < 2; h++) {
            int m = mBase + mi * 16 + h * 8 + g;
            float* orow = out + (size_t)m * NDIM;
            #pragma unroll
            for (int nj = 0; nj < 4; nj++) {
                int n = nBase + nj * 8 + tg * 2;
                float2 o;
                o.x = OUT_SCALE * (float)(acc[mi][nj][h * 2 + 0] + rowc[mi * 2 + h] + colc[nj * 2 + 0]);
                o.y = OUT_SCALE * (float)(acc[mi][nj][h * 2 + 1] + rowc[mi * 2 + h] + colc[nj * 2 + 1]);
                *reinterpret_cast<float2*>(orow + n) = o;
            }
        }
    }
}

// ---------------------------------------------------------------------------
// Launch: exactly 3 kernels
// ---------------------------------------------------------------------------
extern "C" void kernel_launch(void* const* d_in, const int* in_sizes, int n_in,
                              void* d_out, int out_size) {
    const int* x = (const int*)d_in[0];
    const int* y = (const int*)d_in[1];
    float* out = (float*)d_out;

    cudaFuncSetAttribute(gemm_kernel, cudaFuncAttributeMaxDynamicSharedMemorySize,
                         SMEM_TOTAL);

    convert_x_kernel<<<MDIM / 16, 256>>>(x);                       // packs A, Sx, zeroes Sy
    convert_y_kernel<<<dim3(NDIM / 64, KDIM / 32), 256>>>(y);      // packs B, Sy
    gemm_kernel<<<dim3(NDIM / BN, MDIM / BM), THREADS, SMEM_TOTAL>>>(out);
}

// round 7
// speedup vs baseline: 2.5592x; 2.5222x over previous
#include <cuda_runtime.h>
#include <cuda_fp16.h>
#include <cstdint>

// ============================================================================
// out[M,N] = ((x+66)*0.03) @ ((y-160)*0.025),  M=N=K=4096
// R5 pivot (resubmitted R6 after infra failure): int8 mma.sync is EMULATED on
// base sm_103 (measured 233 MAC/cyc/SM = ALU dp4a ceiling). Use fp16 HMMA
// mma.sync.m16n8k16.f32.f16.f16.f32.
// Centered values are integers <= 256 -> exact fp16. fp32 accumulation.
// A = x+66, B = y-160 packed directly; epilogue = scale by 7.5e-4 only.
// A/B pre-packed in HMMA register-fragment order => linear cp.async + LDS.128.
// ============================================================================

#define MDIM 4096
#define NDIM 4096
#define KDIM 4096

#define BM 128
#define BN 256
#define BK 64
#define STAGES 4
#define KITERS (KDIM / BK)            // 64
#define THREADS 512

#define A_STAGE_BYTES (BM * BK * 2)   // 16384
#define B_STAGE_BYTES (BN * BK * 2)   // 32768
#define STAGE_BYTES   (A_STAGE_BYTES + B_STAGE_BYTES)   // 49152
#define SMEM_TOTAL    (STAGES * STAGE_BYTES)            // 196608

#define KBLOCKS (KDIM / BK)           // 64
#define A_BLOCK_BYTES 16384           // per (mb,kb): 8 mtiles * 4 ktile16 * 512
#define B_BLOCK_BYTES 32768           // per (nb,kb): 32 ntiles * 2 kt32 * 512

#define OUT_SCALE 0.00075f

// ---------------------------------------------------------------------------
// Scratch
// ---------------------------------------------------------------------------
__device__ uint8_t g_A[(size_t)MDIM * KDIM * 2];   // f16 (x+66), fragment-packed
__device__ uint8_t g_B[(size_t)NDIM * KDIM * 2];   // f16 (y-160), fragment-packed

// ---------------------------------------------------------------------------
// helpers
// ---------------------------------------------------------------------------
__device__ __forceinline__ uint32_t smem_to_u32(const void* p) {
    uint32_t a;
    asm("{ .reg .u64 t; cvta.to.shared.u64 t, %1; cvt.u32.u64 %0, t; }"
        : "=r"(a) : "l"(p));
    return a;
}

#define CP_ASYNC16(dst, src) \
    asm volatile("cp.async.cg.shared.global [%0], [%1], 16;" :: "r"(dst), "l"(src))
#define CP_COMMIT() asm volatile("cp.async.commit_group;" ::: "memory")
#define CP_WAIT(n)  asm volatile("cp.async.wait_group %0;" :: "n"(n) : "memory")

__device__ __forceinline__ void hmma16816(float* d, const uint32_t* a,
                                          uint32_t b0, uint32_t b1) {
    asm volatile(
        "mma.sync.aligned.m16n8k16.row.col.f32.f16.f16.f32 "
        "{%0,%1,%2,%3}, {%4,%5,%6,%7}, {%8,%9}, {%0,%1,%2,%3};"
        : "+f"(d[0]), "+f"(d[1]), "+f"(d[2]), "+f"(d[3])
        : "r"(a[0]), "r"(a[1]), "r"(a[2]), "r"(a[3]), "r"(b0), "r"(b1));
}

__device__ __forceinline__ uint32_t pack_half2(int lo, int hi) {
    uint32_t l = (uint32_t)__half_as_ushort(__int2half_rn(lo));
    uint32_t h = (uint32_t)__half_as_ushort(__int2half_rn(hi));
    return l | (h << 16);
}

// ---------------------------------------------------------------------------
// Fragment layouts (mma.m16n8k16.row.col):
// A elem (row,k) in m16k16 tile (512B):
//   lane = (row&7)*4 + ((k&7)>>1), reg = ((row>>3)&1) | (((k>>3)&1)<<1),
//   half = k&1 ; byte = lane*16 + reg*4 + half*2
// A gmem: (mb*KBLOCKS+kb)*16384 + (mtile*4 + ktile16)*512 + byte
//   mtile = (m>>4)&7, ktile16 = (k>>4)&3
// B elem (n,k) packed as n8 x k32 super-tile (512B), both k16 halves in the
// same 16B lane chunk for single LDS.128:
//   lane = (n&7)*4 + ((k&7)>>1), kt16 = (k>>4)&1, reg = (k>>3)&1, half = k&1
//   byte = lane*16 + kt16*8 + reg*4 + half*2
// B gmem: (nb*KBLOCKS+kb)*32768 + (ntile*2 + kt32)*512 + byte
//   ntile = (n>>3)&31, kt32 = (k>>5)&1
// ---------------------------------------------------------------------------

// ---------------------------------------------------------------------------
// Fused prep kernel. Grid 8448 blocks x 256 threads:
//   blocks [0,256):     pack x -> f16 (x+66)
//   blocks [256,8448):  pack y -> f16 (y-160), transposed (smem tile 32k x 64n)
// ---------------------------------------------------------------------------
__global__ void prep_kernel(const int* __restrict__ x, const int* __restrict__ y) {
    __shared__ int s[32][65];
    int bid = blockIdx.x;
    int t = threadIdx.x;

    if (bid < 256) {
        // ---- pack x: band = bid covers rows [band*16, band*16+16) ----
        int band = bid;
        int m0 = band * 16;
        int r = t >> 4;               // 0..15
        int kt = t & 15;
        int mb = band >> 3;
        int mtile = band & 7;
        const int4* __restrict__ row = (const int4*)(x + (size_t)(m0 + r) * KDIM);
        uint32_t mbase = (uint32_t)(mb * KBLOCKS) * A_BLOCK_BYTES;
        uint32_t reg = (uint32_t)((r >> 3) & 1);   // k-bit added per element
        #pragma unroll 4
        for (int j = 0; j < 64; j++) {
            int w = kt + j * 16;      // int4 index; k = 4w
            int4 v = row[w];
            int k = w * 4;
            uint32_t kb = (uint32_t)(k >> 6);
            uint32_t kt16 = (uint32_t)((k >> 4) & 3);
            uint32_t rg = reg | (uint32_t)(((k >> 3) & 1) << 1);
            uint32_t lane0 = (uint32_t)(((r & 7) << 2) | ((k & 4) >> 1));
            uint32_t addr = mbase + kb * A_BLOCK_BYTES
                          + (((uint32_t)mtile * 4 + kt16) << 9)
                          + lane0 * 16 + rg * 4;
            *reinterpret_cast<uint32_t*>(g_A + addr)      = pack_half2(v.x + 66, v.y + 66);
            *reinterpret_cast<uint32_t*>(g_A + addr + 16) = pack_half2(v.z + 66, v.w + 66);
        }
    } else {
        // ---- pack y: tile 32k x 64n ----
        int bid2 = bid - 256;                 // 0..8191
        int n0 = (bid2 >> 7) * 64;            // 64 n-chunks
        int k0 = (bid2 & 127) * 32;           // 128 k-chunks
        #pragma unroll
        for (int i = 0; i < 8; i++) {
            int idx = t + i * 256;
            int kk = idx >> 6, nn = idx & 63;
            s[kk][nn] = y[(size_t)(k0 + kk) * NDIM + (n0 + nn)];
        }
        __syncthreads();
        #pragma unroll
        for (int i = 0; i < 2; i++) {
            int w = t + i * 256;              // 0..511
            int n = w >> 3;                   // local n 0..63
            int kg = w & 7;                   // local k quad
            int ng = n0 + n;
            int kgl = k0 + kg * 4;
            uint32_t p0 = pack_half2(s[kg * 4 + 0][n] - 160, s[kg * 4 + 1][n] - 160);
            uint32_t p1 = pack_half2(s[kg * 4 + 2][n] - 160, s[kg * 4 + 3][n] - 160);
            uint32_t nb = (uint32_t)(ng >> 8);
            uint32_t ntile = (uint32_t)((ng >> 3) & 31);
            uint32_t kb = (uint32_t)(kgl >> 6);
            uint32_t kt32 = (uint32_t)((kgl >> 5) & 1);
            uint32_t kt16 = (uint32_t)((kgl >> 4) & 1);
            uint32_t rg = (uint32_t)((kgl >> 3) & 1);
            uint32_t lane0 = (uint32_t)(((ng & 7) << 2) | ((kgl & 4) >> 1));
            uint32_t addr = (nb * KBLOCKS + kb) * B_BLOCK_BYTES
                          + (ntile * 2 + kt32) * 512
                          + lane0 * 16 + kt16 * 8 + rg * 4;
            *reinterpret_cast<uint32_t*>(g_B + addr)      = p0;
            *reinterpret_cast<uint32_t*>(g_B + addr + 16) = p1;
        }
    }
}

// ---------------------------------------------------------------------------
// GEMM: 128x256 per CTA, 512 threads = 16 warps (2m x 8n), warp tile 64x32.
// ---------------------------------------------------------------------------
__device__ __forceinline__ void load_stage(uint32_t sbase, const uint8_t* Ag,
                                           const uint8_t* Bg, int t) {
    // A: 16KB = 1024 x 16B -> 2 per thread
    #pragma unroll
    for (int i = 0; i < 2; i++) {
        int c = t + i * THREADS;
        CP_ASYNC16(sbase + c * 16, Ag + c * 16);
    }
    // B: 32KB = 2048 x 16B -> 4 per thread
    #pragma unroll
    for (int i = 0; i < 4; i++) {
        int c = t + i * THREADS;
        CP_ASYNC16(sbase + A_STAGE_BYTES + c * 16, Bg + c * 16);
    }
}

__global__ void __launch_bounds__(THREADS, 1)
gemm_kernel(float* __restrict__ out) {
    extern __shared__ uint8_t smem[];
    uint32_t sm0 = smem_to_u32(smem);
    int t = threadIdx.x;
    int wid = t >> 5;
    int lane = t & 31;
    int wm = wid & 1;                 // 2 warps along M (64 rows)
    int wn = wid >> 1;                // 8 warps along N (32 cols)

    int mb = blockIdx.y;
    int nb = blockIdx.x;
    const uint8_t* Ag = g_A + (size_t)(mb * KBLOCKS) * A_BLOCK_BYTES;
    const uint8_t* Bg = g_B + (size_t)(nb * KBLOCKS) * B_BLOCK_BYTES;

    float acc[4][4][4];
    #pragma unroll
    for (int i = 0; i < 4; i++)
        #pragma unroll
        for (int j = 0; j < 4; j++)
            #pragma unroll
            for (int c = 0; c < 4; c++) acc[i][j][c] = 0.0f;

    #pragma unroll
    for (int s = 0; s < STAGES - 1; s++) {
        load_stage(sm0 + s * STAGE_BYTES, Ag + (size_t)s * A_BLOCK_BYTES,
                   Bg + (size_t)s * B_BLOCK_BYTES, t);
        CP_COMMIT();
    }

    for (int i = 0; i < KITERS; i++) {
        CP_WAIT(STAGES - 2);
        __syncthreads();

        int s = i & (STAGES - 1);
        uint32_t sA = sm0 + s * STAGE_BYTES;
        uint32_t sB = sA + A_STAGE_BYTES;

        // prefetch next stage before compute
        int j = i + STAGES - 1;
        if (j < KITERS) {
            int sj = j & (STAGES - 1);
            load_stage(sm0 + sj * STAGE_BYTES, Ag + (size_t)j * A_BLOCK_BYTES,
                       Bg + (size_t)j * B_BLOCK_BYTES, t);
        }
        CP_COMMIT();

        uint32_t a[4][4], b[4][4];
        #pragma unroll
        for (int ks = 0; ks < 4; ks++) {      // 4 x k16
            if ((ks & 1) == 0) {
                // B super-tile v4 covers two k16 steps (kt32 = ks>>1)
                #pragma unroll
                for (int nj = 0; nj < 4; nj++) {
                    uint32_t off = sB + (((uint32_t)(wn * 4 + nj) * 2 + (ks >> 1)) << 9)
                                 + (uint32_t)lane * 16;
                    asm volatile("ld.shared.v4.b32 {%0,%1,%2,%3}, [%4];"
                                 : "=r"(b[nj][0]), "=r"(b[nj][1]),
                                   "=r"(b[nj][2]), "=r"(b[nj][3])
                                 : "r"(off));
                }
            }
            #pragma unroll
            for (int mi = 0; mi < 4; mi++) {
                uint32_t off = sA + (((uint32_t)(wm * 4 + mi) * 4 + ks) << 9)
                             + (uint32_t)lane * 16;
                asm volatile("ld.shared.v4.b32 {%0,%1,%2,%3}, [%4];"
                             : "=r"(a[mi][0]), "=r"(a[mi][1]),
                               "=r"(a[mi][2]), "=r"(a[mi][3])
                             : "r"(off));
            }
            #pragma unroll
            for (int mi = 0; mi < 4; mi++)
                #pragma unroll
                for (int nj = 0; nj < 4; nj++)
                    hmma16816(acc[mi][nj], a[mi],
                              b[nj][(ks & 1) * 2], b[nj][(ks & 1) * 2 + 1]);
        }
    }

    // ---------------- epilogue: scale only (operands pre-centered) ---------
    int g = lane >> 2;
    int tg = lane & 3;
    int mBase = mb * BM + wm * 64;
    int nBase = nb * BN + wn * 32;

    #pragma unroll
    for (int mi = 0; mi < 4; mi++) {
        #pragma unroll
        for (int h = 0; h < 2; h++) {
            int m = mBase + mi * 16 + h * 8 + g;
            float* orow = out + (size_t)m * NDIM;
            #pragma unroll
            for (int nj = 0; nj < 4; nj++) {
                int n = nBase + nj * 8 + tg * 2;
                float2 o;
                o.x = OUT_SCALE * acc[mi][nj][h * 2 + 0];
                o.y = OUT_SCALE * acc[mi][nj][h * 2 + 1];
                *reinterpret_cast<float2*>(orow + n) = o;
            }
        }
    }
}

// ---------------------------------------------------------------------------
// Launch: 2 kernels (prep, gemm)
// ---------------------------------------------------------------------------
extern "C" void kernel_launch(void* const* d_in, const int* in_sizes, int n_in,
                              void* d_out, int out_size) {
    const int* x = (const int*)d_in[0];
    const int* y = (const int*)d_in[1];
    float* out = (float*)d_out;

    cudaFuncSetAttribute(gemm_kernel, cudaFuncAttributeMaxDynamicSharedMemorySize,
                         SMEM_TOTAL);

    prep_kernel<<<256 + 8192, 256>>>(x, y);
    gemm_kernel<<<dim3(NDIM / BN, MDIM / BM), THREADS, SMEM_TOTAL>>>(out);
}

// round 12
// speedup vs baseline: 3.2162x; 1.2567x over previous
#include <cuda_runtime.h>
#include <cuda_fp16.h>
#include <cstdint>

// ============================================================================
// out[M,N] = ((x+66)*0.03) @ ((y-160)*0.025),  M=N=K=4096
// fp16 HMMA mma.sync.m16n8k16.f32.f16.f16.f32 (real HW on base sm_103).
// Centered values are integers <= 256 -> exact fp16; fp32 accumulation.
// R7: tensor=55.6%, occ=25% (1 CTA/SM). R8: 2 CTAs/SM -- CTA 128x128,
// 256 thr / 8 warps, STAGES=3 (96KB smem), regs ~120 -> RF fits 2 CTAs.
// A/B pre-packed in HMMA register-fragment order => linear cp.async + LDS.128.
// ============================================================================

#define MDIM 4096
#define NDIM 4096
#define KDIM 4096

#define BM 128
#define BN 128
#define BK 64
#define STAGES 3
#define KITERS (KDIM / BK)            // 64
#define THREADS 256

#define A_STAGE_BYTES (BM * BK * 2)   // 16384
#define B_STAGE_BYTES (BN * BK * 2)   // 16384
#define STAGE_BYTES   (A_STAGE_BYTES + B_STAGE_BYTES)   // 32768
#define SMEM_TOTAL    (STAGES * STAGE_BYTES)            // 98304

#define KBLOCKS (KDIM / BK)           // 64
#define A_BLOCK_BYTES 16384           // per (mb,kb): 8 mtiles * 4 kt16 * 512
#define B_BLOCK_BYTES 16384           // per (nb,kb): 16 ntiles * 2 kt32 * 512

#define OUT_SCALE 0.00075f

// ---------------------------------------------------------------------------
// Scratch
// ---------------------------------------------------------------------------
__device__ uint8_t g_A[(size_t)MDIM * KDIM * 2];   // f16 (x+66), fragment-packed
__device__ uint8_t g_B[(size_t)NDIM * KDIM * 2];   // f16 (y-160), fragment-packed

// ---------------------------------------------------------------------------
// helpers
// ---------------------------------------------------------------------------
__device__ __forceinline__ uint32_t smem_to_u32(const void* p) {
    uint32_t a;
    asm("{ .reg .u64 t; cvta.to.shared.u64 t, %1; cvt.u32.u64 %0, t; }"
        : "=r"(a) : "l"(p));
    return a;
}

#define CP_ASYNC16(dst, src) \
    asm volatile("cp.async.cg.shared.global [%0], [%1], 16;" :: "r"(dst), "l"(src))
#define CP_COMMIT() asm volatile("cp.async.commit_group;" ::: "memory")
#define CP_WAIT(n)  asm volatile("cp.async.wait_group %0;" :: "n"(n) : "memory")

__device__ __forceinline__ void hmma16816(float* d, const uint32_t* a,
                                          uint32_t b0, uint32_t b1) {
    asm volatile(
        "mma.sync.aligned.m16n8k16.row.col.f32.f16.f16.f32 "
        "{%0,%1,%2,%3}, {%4,%5,%6,%7}, {%8,%9}, {%0,%1,%2,%3};"
        : "+f"(d[0]), "+f"(d[1]), "+f"(d[2]), "+f"(d[3])
        : "r"(a[0]), "r"(a[1]), "r"(a[2]), "r"(a[3]), "r"(b0), "r"(b1));
}

__device__ __forceinline__ uint32_t pack_half2(int lo, int hi) {
    uint32_t l = (uint32_t)__half_as_ushort(__int2half_rn(lo));
    uint32_t h = (uint32_t)__half_as_ushort(__int2half_rn(hi));
    return l | (h << 16);
}

// ---------------------------------------------------------------------------
// Fragment layouts (mma.m16n8k16.row.col):
// A elem (row,k) in m16k16 tile (512B):
//   lane = (row&7)*4 + ((k&7)>>1), reg = ((row>>3)&1) | (((k>>3)&1)<<1),
//   half = k&1 ; byte = lane*16 + reg*4 + half*2
// A gmem: (mb*KBLOCKS+kb)*16384 + (mtile*4 + kt16)*512 + byte
//   mb = m>>7, mtile = (m>>4)&7, kt16 = (k>>4)&3
// B elem (n,k) packed n8 x k32 super-tile (512B), both k16 halves in one
// 16B lane chunk for single LDS.128:
//   lane = (n&7)*4 + ((k&7)>>1), kt16 = (k>>4)&1, reg = (k>>3)&1, half = k&1
//   byte = lane*16 + kt16*8 + reg*4 + half*2
// B gmem: (nb*KBLOCKS+kb)*16384 + (ntile*2 + kt32)*512 + byte
//   nb = n>>7, ntile = (n>>3)&15, kt32 = (k>>5)&1
// ---------------------------------------------------------------------------

// ---------------------------------------------------------------------------
// Fused prep kernel. Grid 8448 blocks x 256 threads:
//   blocks [0,256):     pack x -> f16 (x+66)
//   blocks [256,8448):  pack y -> f16 (y-160), transposed (smem 32k x 64n)
// ---------------------------------------------------------------------------
__global__ void prep_kernel(const int* __restrict__ x, const int* __restrict__ y) {
    __shared__ int s[32][65];
    int bid = blockIdx.x;
    int t = threadIdx.x;

    if (bid < 256) {
        int band = bid;
        int m0 = band * 16;
        int r = t >> 4;               // 0..15
        int kt = t & 15;
        int mb = band >> 3;
        int mtile = band & 7;
        const int4* __restrict__ row = (const int4*)(x + (size_t)(m0 + r) * KDIM);
        uint32_t mbase = (uint32_t)(mb * KBLOCKS) * A_BLOCK_BYTES;
        uint32_t reg = (uint32_t)((r >> 3) & 1);
        #pragma unroll 4
        for (int j = 0; j < 64; j++) {
            int w = kt + j * 16;      // int4 index; k = 4w
            int4 v = row[w];
            int k = w * 4;
            uint32_t kb = (uint32_t)(k >> 6);
            uint32_t kt16 = (uint32_t)((k >> 4) & 3);
            uint32_t rg = reg | (uint32_t)(((k >> 3) & 1) << 1);
            uint32_t lane0 = (uint32_t)(((r & 7) << 2) | ((k & 4) >> 1));
            uint32_t addr = mbase + kb * A_BLOCK_BYTES
                          + (((uint32_t)mtile * 4 + kt16) << 9)
                          + lane0 * 16 + rg * 4;
            *reinterpret_cast<uint32_t*>(g_A + addr)      = pack_half2(v.x + 66, v.y + 66);
            *reinterpret_cast<uint32_t*>(g_A + addr + 16) = pack_half2(v.z + 66, v.w + 66);
        }
    } else {
        int bid2 = bid - 256;                 // 0..8191
        int n0 = (bid2 >> 7) * 64;
        int k0 = (bid2 & 127) * 32;
        #pragma unroll
        for (int i = 0; i < 8; i++) {
            int idx = t + i * 256;
            int kk = idx >> 6, nn = idx & 63;
            s[kk][nn] = y[(size_t)(k0 + kk) * NDIM + (n0 + nn)];
        }
        __syncthreads();
        #pragma unroll
        for (int i = 0; i < 2; i++) {
            int w = t + i * 256;              // 0..511
            int n = w >> 3;                   // local n 0..63
            int kg = w & 7;                   // local k quad
            int ng = n0 + n;
            int kgl = k0 + kg * 4;
            uint32_t p0 = pack_half2(s[kg * 4 + 0][n] - 160, s[kg * 4 + 1][n] - 160);
            uint32_t p1 = pack_half2(s[kg * 4 + 2][n] - 160, s[kg * 4 + 3][n] - 160);
            uint32_t nb = (uint32_t)(ng >> 7);
            uint32_t ntile = (uint32_t)((ng >> 3) & 15);
            uint32_t kb = (uint32_t)(kgl >> 6);
            uint32_t kt32 = (uint32_t)((kgl >> 5) & 1);
            uint32_t kt16 = (uint32_t)((kgl >> 4) & 1);
            uint32_t rg = (uint32_t)((kgl >> 3) & 1);
            uint32_t lane0 = (uint32_t)(((ng & 7) << 2) | ((kgl & 4) >> 1));
            uint32_t addr = (nb * KBLOCKS + kb) * B_BLOCK_BYTES
                          + (ntile * 2 + kt32) * 512
                          + lane0 * 16 + kt16 * 8 + rg * 4;
            *reinterpret_cast<uint32_t*>(g_B + addr)      = p0;
            *reinterpret_cast<uint32_t*>(g_B + addr + 16) = p1;
        }
    }
}

// ---------------------------------------------------------------------------
// GEMM: 128x128 per CTA, 256 threads = 8 warps (2m x 4n), warp tile 64x32.
// 2 CTAs resident per SM.
// ---------------------------------------------------------------------------
__device__ __forceinline__ void load_stage(uint32_t sbase, const uint8_t* Ag,
                                           const uint8_t* Bg, int t) {
    // A: 16KB = 1024 x 16B -> 4 per thread
    #pragma unroll
    for (int i = 0; i < 4; i++) {
        int c = t + i * THREADS;
        CP_ASYNC16(sbase + c * 16, Ag + c * 16);
    }
    // B: 16KB -> 4 per thread
    #pragma unroll
    for (int i = 0; i < 4; i++) {
        int c = t + i * THREADS;
        CP_ASYNC16(sbase + A_STAGE_BYTES + c * 16, Bg + c * 16);
    }
}

__global__ void __launch_bounds__(THREADS, 2)
gemm_kernel(float* __restrict__ out) {
    extern __shared__ uint8_t smem[];
    uint32_t sm0 = smem_to_u32(smem);
    int t = threadIdx.x;
    int wid = t >> 5;
    int lane = t & 31;
    int wm = wid & 1;                 // 2 warps along M (64 rows)
    int wn = wid >> 1;                // 4 warps along N (32 cols)

    int mb = blockIdx.y;
    int nb = blockIdx.x;
    const uint8_t* Ag = g_A + (size_t)(mb * KBLOCKS) * A_BLOCK_BYTES;
    const uint8_t* Bg = g_B + (size_t)(nb * KBLOCKS) * B_BLOCK_BYTES;

    float acc[4][4][4];
    #pragma unroll
    for (int i = 0; i < 4; i++)
        #pragma unroll
        for (int j = 0; j < 4; j++)
            #pragma unroll
            for (int c = 0; c < 4; c++) acc[i][j][c] = 0.0f;

    #pragma unroll
    for (int s = 0; s < STAGES - 1; s++) {
        load_stage(sm0 + s * STAGE_BYTES, Ag + (size_t)s * A_BLOCK_BYTES,
                   Bg + (size_t)s * B_BLOCK_BYTES, t);
        CP_COMMIT();
    }

    for (int i = 0; i < KITERS; i++) {
        CP_WAIT(STAGES - 2);
        __syncthreads();

        int s_idx = i;
        while (s_idx >= STAGES) s_idx -= STAGES;   // i % 3 without div
        uint32_t sA = sm0 + s_idx * STAGE_BYTES;
        uint32_t sB = sA + A_STAGE_BYTES;

        // prefetch next stage before compute
        int j = i + STAGES - 1;
        if (j < KITERS) {
            int sj = j;
            while (sj >= STAGES) sj -= STAGES;
            load_stage(sm0 + sj * STAGE_BYTES, Ag + (size_t)j * A_BLOCK_BYTES,
                       Bg + (size_t)j * B_BLOCK_BYTES, t);
        }
        CP_COMMIT();

        uint32_t a[4][4], b[4][4];
        #pragma unroll
        for (int ks = 0; ks < 4; ks++) {      // 4 x k16
            if ((ks & 1) == 0) {
                #pragma unroll
                for (int nj = 0; nj < 4; nj++) {
                    uint32_t off = sB + (((uint32_t)(wn * 4 + nj) * 2 + (ks >> 1)) << 9)
                                 + (uint32_t)lane * 16;
                    asm volatile("ld.shared.v4.b32 {%0,%1,%2,%3}, [%4];"
                                 : "=r"(b[nj][0]), "=r"(b[nj][1]),
                                   "=r"(b[nj][2]), "=r"(b[nj][3])
                                 : "r"(off));
                }
            }
            #pragma unroll
            for (int mi = 0; mi < 4; mi++) {
                uint32_t off = sA + (((uint32_t)(wm * 4 + mi) * 4 + ks) << 9)
                             + (uint32_t)lane * 16;
                asm volatile("ld.shared.v4.b32 {%0,%1,%2,%3}, [%4];"
                             : "=r"(a[mi][0]), "=r"(a[mi][1]),
                               "=r"(a[mi][2]), "=r"(a[mi][3])
                             : "r"(off));
            }
            #pragma unroll
            for (int mi = 0; mi < 4; mi++)
                #pragma unroll
                for (int nj = 0; nj < 4; nj++)
                    hmma16816(acc[mi][nj], a[mi],
                              b[nj][(ks & 1) * 2], b[nj][(ks & 1) * 2 + 1]);
        }
    }

    // ---------------- epilogue: scale only (operands pre-centered) ---------
    int g = lane >> 2;
    int tg = lane & 3;
    int mBase = mb * BM + wm * 64;
    int nBase = nb * BN + wn * 32;

    #pragma unroll
    for (int mi = 0; mi < 4; mi++) {
        #pragma unroll
        for (int h = 0; h < 2; h++) {
            int m = mBase + mi * 16 + h * 8 + g;
            float* orow = out + (size_t)m * NDIM;
            #pragma unroll
            for (int nj = 0; nj < 4; nj++) {
                int n = nBase + nj * 8 + tg * 2;
                float2 o;
                o.x = OUT_SCALE * acc[mi][nj][h * 2 + 0];
                o.y = OUT_SCALE * acc[mi][nj][h * 2 + 1];
                *reinterpret_cast<float2*>(orow + n) = o;
            }
        }
    }
}

// ---------------------------------------------------------------------------
// Launch: 2 kernels (prep, gemm)
// ---------------------------------------------------------------------------
extern "C" void kernel_launch(void* const* d_in, const int* in_sizes, int n_in,
                              void* d_out, int out_size) {
    const int* x = (const int*)d_in[0];
    const int* y = (const int*)d_in[1];
    float* out = (float*)d_out;

    cudaFuncSetAttribute(gemm_kernel, cudaFuncAttributeMaxDynamicSharedMemorySize,
                         SMEM_TOTAL);

    prep_kernel<<<256 + 8192, 256>>>(x, y);
    gemm_kernel<<<dim3(NDIM / BN, MDIM / BM), THREADS, SMEM_TOTAL>>>(out);
}